// round 3
// baseline (speedup 1.0000x reference)
#include <cuda_runtime.h>
#include <math.h>

#define NR    8192
#define F_IN  128
#define F_OUT 64
#define ALPHA 0.2f
#define LDW   68          // padded row stride (65 used) for scan arrays
#define NSEG  64          // 8192 / 128 element-segments
#define SEGSZ 128
#define NB    4096        // value buckets
#define NCH   16          // scatter chunks
#define CHSZ  512

// ---------------- scratch (device globals; no allocs allowed) ----------------
__device__ float g_Wh[NR * F_OUT];        // 2 MB
__device__ float g_s[NR];
__device__ float g_d[NR];
__device__ float g_dmax, g_dmin, g_scale;
__device__ int   g_bkt[NR];
__device__ int   g_chist[NB * NCH];
__device__ int   g_choff[NB * NCH];
__device__ int   g_off[NB + 1];
__device__ int   g_ord[NR];
__device__ float g_dord[NR];
__device__ float g_locPre[NR * LDW];      // D-weighted exclusive prefix (within segment)
__device__ float g_locSuf[NR * LDW];      // B-weighted inclusive suffix (within segment)
__device__ float g_segPre[NSEG * LDW];
__device__ float g_segSuf[NSEG * LDW];
__device__ float g_offPre[(NSEG + 1) * LDW];
__device__ float g_offSuf[NSEG * LDW];

// Monotone bucket-value map. MUST be identical fp ops for elements & thresholds
// (explicit rn intrinsics prevent FMA contraction differences across kernels).
__device__ __forceinline__ float bval(float x, float dmin, float scale)
{
    return fminf(__fmul_rn(__fsub_rn(x, dmin), scale), (float)(NB - 1));
}

// ---------------------------------------------------------------------------
// Kernel A: Wh = h @ W ; s = Wh @ a1 ; d = Wh @ a2
// ---------------------------------------------------------------------------
__global__ __launch_bounds__(128) void wh_kernel(const float* __restrict__ h,
                                                 const float* __restrict__ W,
                                                 const float* __restrict__ a)
{
    __shared__ float h_sh[16][F_IN];
    __shared__ float W_sh[F_IN][F_OUT];
    __shared__ float wh_sh[16][F_OUT];
    __shared__ float a_sh[2 * F_OUT];

    const int tid = threadIdx.x;
    const int row_base = blockIdx.x * 16;

    const float4* Wv  = (const float4*)W;
    float4*       Wsv = (float4*)W_sh;
#pragma unroll
    for (int k = 0; k < 16; k++) Wsv[tid + k * 128] = Wv[tid + k * 128];

    const float4* hv  = (const float4*)(h + (size_t)row_base * F_IN);
    float4*       hsv = (float4*)h_sh;
#pragma unroll
    for (int k = 0; k < 4; k++) hsv[tid + k * 128] = hv[tid + k * 128];

    a_sh[tid] = a[tid];
    __syncthreads();

    const int c  = tid & 63;
    const int rh = tid >> 6;

    float acc[8];
#pragma unroll
    for (int r = 0; r < 8; r++) acc[r] = 0.f;

#pragma unroll 8
    for (int k = 0; k < F_IN; k++) {
        float wv = W_sh[k][c];
#pragma unroll
        for (int r = 0; r < 8; r++)
            acc[r] = fmaf(h_sh[rh * 8 + r][k], wv, acc[r]);
    }

#pragma unroll
    for (int r = 0; r < 8; r++) {
        wh_sh[rh * 8 + r][c] = acc[r];
        g_Wh[(size_t)(row_base + rh * 8 + r) * F_OUT + c] = acc[r];
    }
    __syncthreads();

    if (tid < 16) {
        float sv = 0.f, dv = 0.f;
#pragma unroll
        for (int cc = 0; cc < F_OUT; cc++) {
            float v = wh_sh[tid][cc];
            sv = fmaf(v, a_sh[cc], sv);
            dv = fmaf(v, a_sh[F_OUT + cc], dv);
        }
        g_s[row_base + tid] = sv;
        g_d[row_base + tid] = dv;
    }
}

// ---------------------------------------------------------------------------
// Kernel B: dmin/dmax of d + bucket scale (1 block)
// ---------------------------------------------------------------------------
__global__ __launch_bounds__(1024) void range_kernel()
{
    __shared__ float smx[32], smn[32];
    const int t = threadIdx.x;
    float mx = -1e30f, mn = 1e30f;
    for (int i = t; i < NR; i += 1024) {
        float v = g_d[i];
        mx = fmaxf(mx, v);
        mn = fminf(mn, v);
    }
#pragma unroll
    for (int o = 16; o; o >>= 1) {
        mx = fmaxf(mx, __shfl_xor_sync(~0u, mx, o));
        mn = fminf(mn, __shfl_xor_sync(~0u, mn, o));
    }
    if ((t & 31) == 0) { smx[t >> 5] = mx; smn[t >> 5] = mn; }
    __syncthreads();
    if (t < 32) {
        mx = smx[t]; mn = smn[t];
#pragma unroll
        for (int o = 16; o; o >>= 1) {
            mx = fmaxf(mx, __shfl_xor_sync(~0u, mx, o));
            mn = fminf(mn, __shfl_xor_sync(~0u, mn, o));
        }
        if (t == 0) {
            g_dmax = mx;
            g_dmin = mn;
            float r = mx - mn;
            g_scale = (r > 0.f) ? (float)NB * (1.f - 1e-6f) / r : 0.f;
        }
    }
}

// ---------------------------------------------------------------------------
// Kernel H: per-chunk bucket histograms (deterministic integer counts)
// ---------------------------------------------------------------------------
__global__ __launch_bounds__(CHSZ) void hist_kernel()
{
    __shared__ int hist[NB];   // 16 KB
    const int t = threadIdx.x, blk = blockIdx.x;
    for (int i = t; i < NB; i += CHSZ) hist[i] = 0;
    __syncthreads();

    const int j = blk * CHSZ + t;
    const float dmin = g_dmin, scale = g_scale;
    const int b = (int)bval(g_d[j], dmin, scale);   // always >= 0 for elements
    g_bkt[j] = b;
    atomicAdd(&hist[b], 1);
    __syncthreads();

    for (int i = t; i < NB; i += CHSZ) g_chist[i * NCH + blk] = hist[i];
}

// ---------------------------------------------------------------------------
// Kernel O: exclusive scan of 65536 (bucket,chunk) counts (1 block)
// ---------------------------------------------------------------------------
__global__ __launch_bounds__(1024) void scanoff_kernel()
{
    __shared__ int ssum[1024];
    const int t = threadIdx.x;
    const int base = t * 64;

    int s = 0;
#pragma unroll 8
    for (int i = 0; i < 64; i++) s += g_chist[base + i];
    ssum[t] = s;
    __syncthreads();

    // inclusive Hillis-Steele scan of 1024 partials
    for (int d = 1; d < 1024; d <<= 1) {
        int add = (t >= d) ? ssum[t - d] : 0;
        __syncthreads();
        ssum[t] += add;
        __syncthreads();
    }

    int run = (t == 0) ? 0 : ssum[t - 1];
#pragma unroll 8
    for (int i = 0; i < 64; i++) {
        int v = base + i;
        g_choff[v] = run;
        if ((v & (NCH - 1)) == 0) g_off[v >> 4] = run;  // bucket start
        run += g_chist[v];
    }
    if (t == 0) g_off[NB] = NR;
}

// ---------------------------------------------------------------------------
// Kernel Sc: stable scatter into bucket order (deterministic)
// ---------------------------------------------------------------------------
__global__ __launch_bounds__(CHSZ) void scatter_kernel()
{
    __shared__ int bk[CHSZ];
    const int t = threadIdx.x, blk = blockIdx.x;
    const int j = blk * CHSZ + t;
    const int b = g_bkt[j];
    bk[t] = b;
    __syncthreads();

    int lr = 0;
#pragma unroll 8
    for (int k = 0; k < CHSZ; k++)
        lr += (k < t && bk[k] == b);

    const int pos = g_choff[b * NCH + blk] + lr;
    g_ord[pos]  = j;
    g_dord[pos] = g_d[j];
}

// ---------------------------------------------------------------------------
// Kernel S1: per-segment element scans (prefix D-weighted excl, suffix B incl)
// ---------------------------------------------------------------------------
__global__ __launch_bounds__(128) void scan_kernel()
{
    __shared__ float wh[SEGSZ][65];
    __shared__ float Bsh[SEGSZ], Dsh[SEGSZ];

    const int g = blockIdx.x;
    const int t = threadIdx.x;
    const int base = g * SEGSZ;

    const int src = g_ord[base + t];
    const float4* wr = (const float4*)(g_Wh + (size_t)src * F_OUT);
#pragma unroll
    for (int i = 0; i < 16; i++) {
        float4 v = wr[i];
        wh[t][i * 4 + 0] = v.x;
        wh[t][i * 4 + 1] = v.y;
        wh[t][i * 4 + 2] = v.z;
        wh[t][i * 4 + 3] = v.w;
    }
    const float dm = g_dmax;
    const float dv = g_dord[base + t];
    Bsh[t] = __expf(dv - dm);
    Dsh[t] = __expf(ALPHA * (dv - dm));
    __syncthreads();

    if (t < 65) {
        float acc = 0.f;
        for (int k = 0; k < SEGSZ; k++) {
            g_locPre[(size_t)(base + k) * LDW + t] = acc;
            float x = (t < 64) ? wh[k][t] : 1.f;
            acc = fmaf(Dsh[k], x, acc);
        }
        g_segPre[g * LDW + t] = acc;

        float acc2 = 0.f;
        for (int k = SEGSZ - 1; k >= 0; k--) {
            float x = (t < 64) ? wh[k][t] : 1.f;
            acc2 = fmaf(Bsh[k], x, acc2);
            g_locSuf[(size_t)(base + k) * LDW + t] = acc2;
        }
        g_segSuf[g * LDW + t] = acc2;
    }
}

// ---------------------------------------------------------------------------
// Kernel S2: scan segment totals (1 block)
// ---------------------------------------------------------------------------
__global__ __launch_bounds__(128) void segscan_kernel()
{
    const int t = threadIdx.x;
    if (t >= 65) return;
    float acc = 0.f;
    for (int g = 0; g < NSEG; g++) {
        g_offPre[g * LDW + t] = acc;
        acc += g_segPre[g * LDW + t];
    }
    g_offPre[NSEG * LDW + t] = acc;

    float acc2 = 0.f;
    for (int g = NSEG - 1; g >= 0; g--) {
        g_offSuf[g * LDW + t] = acc2;
        acc2 += g_segSuf[g * LDW + t];
    }
}

// ---------------------------------------------------------------------------
// Kernel F: warp-per-row combine. Split = bucket lookup (no search);
// boundary bucket iterated exactly; coalesced reads; ELU output.
// ---------------------------------------------------------------------------
__global__ __launch_bounds__(256) void final_kernel(float* __restrict__ out)
{
    const int t = threadIdx.x;
    const int w = t >> 5, l = t & 31;
    const int i = blockIdx.x * 8 + w;

    const float s     = g_s[i];
    const float dm    = g_dmax;
    const float dmin  = g_dmin;
    const float scale = g_scale;

    const float xm = s + dm;
    const float m  = fmaxf(xm, ALPHA * xm);
    const float A  = __expf(xm - m);
    const float C  = __expf(ALPHA * xm - m);
    const float th = -s;

    const float tb = bval(th, dmin, scale);
    int e0 = 0, e1 = 0;
    if (tb >= 0.f) {
        int b = (int)tb;
        e0 = g_off[b];
        e1 = g_off[b + 1];
    }

    // prefix over [0, e0) with D weights
    float pre_l, pre_h, pre_z;
    if (e0 < NR) {
        const int sg = e0 >> 7;
        const float* oP = g_offPre + sg * LDW;
        const float* lP = g_locPre + (size_t)e0 * LDW;
        pre_l = oP[l] + lP[l];
        pre_h = oP[32 + l] + lP[32 + l];
        pre_z = oP[64] + lP[64];
    } else {
        const float* oP = g_offPre + NSEG * LDW;
        pre_l = oP[l];
        pre_h = oP[32 + l];
        pre_z = oP[64];
    }

    // suffix over [e1, NR) with B weights
    float suf_l = 0.f, suf_h = 0.f, suf_z = 0.f;
    if (e1 < NR) {
        const int sg = e1 >> 7;
        const float* oS = g_offSuf + sg * LDW;
        const float* lS = g_locSuf + (size_t)e1 * LDW;
        suf_l = oS[l] + lS[l];
        suf_h = oS[32 + l] + lS[32 + l];
        suf_z = oS[64] + lS[64];
    }

    // boundary bucket [e0, e1): exact per-element compare
    for (int e = e0; e < e1; e++) {
        const float de = g_dord[e];
        const int   je = g_ord[e];
        const float* wr = g_Wh + (size_t)je * F_OUT;
        const float x1 = wr[l], x2 = wr[32 + l];
        if (de <= th) {
            const float wd = __expf(ALPHA * (de - dm));
            pre_l = fmaf(wd, x1, pre_l);
            pre_h = fmaf(wd, x2, pre_h);
            pre_z += wd;
        } else {
            const float wb = __expf(de - dm);
            suf_l = fmaf(wb, x1, suf_l);
            suf_h = fmaf(wb, x2, suf_h);
            suf_z += wb;
        }
    }

    const float Z  = fmaf(A, suf_z, C * pre_z);
    const float rz = 1.f / Z;
    const float v1 = fmaf(A, suf_l, C * pre_l) * rz;
    const float v2 = fmaf(A, suf_h, C * pre_h) * rz;

    out[(size_t)i * F_OUT + l]      = (v1 > 0.f) ? v1 : expm1f(v1);
    out[(size_t)i * F_OUT + 32 + l] = (v2 > 0.f) ? v2 : expm1f(v2);
}

// ---------------------------------------------------------------------------
extern "C" void kernel_launch(void* const* d_in, const int* in_sizes, int n_in,
                              void* d_out, int out_size)
{
    const float* h = (const float*)d_in[0];
    const float* W = (const float*)d_in[1];
    const float* a = (const float*)d_in[2];
    float* out = (float*)d_out;

    wh_kernel<<<NR / 16, 128>>>(h, W, a);
    range_kernel<<<1, 1024>>>();
    hist_kernel<<<NCH, CHSZ>>>();
    scanoff_kernel<<<1, 1024>>>();
    scatter_kernel<<<NCH, CHSZ>>>();
    scan_kernel<<<NSEG, 128>>>();
    segscan_kernel<<<1, 128>>>();
    final_kernel<<<NR / 8, 256>>>(out);
}

// round 4
// speedup vs baseline: 2.5167x; 2.5167x over previous
#include <cuda_runtime.h>
#include <math.h>

#define NR    8192
#define F_IN  128
#define F_OUT 64
#define ALPHA 0.2f
#define LDW   68          // padded row stride (65 used) for scan arrays
#define NSEG  64          // 8192 / 128 element-segments
#define SEGSZ 128
#define NB    4096        // value buckets
#define NCH   16          // scatter chunks
#define CHSZ  512

// ---------------- scratch (device globals; no allocs allowed) ----------------
__device__ float g_Wh[NR * F_OUT];        // 2 MB
__device__ float g_s[NR];
__device__ float g_d[NR];
__device__ float g_dmax, g_dmin, g_scale;
__device__ int   g_bkt[NR];
__device__ int   g_chist[NB * NCH];
__device__ int   g_choff[NB * NCH];
__device__ int   g_off[NB + 1];
__device__ int   g_ord[NR];
__device__ float g_dord[NR];
__device__ float g_locPre[NR * LDW];      // D-weighted exclusive prefix (within segment)
__device__ float g_locSuf[NR * LDW];      // B-weighted inclusive suffix (within segment)
__device__ float g_segPre[NSEG * LDW];
__device__ float g_segSuf[NSEG * LDW];
__device__ float g_offPre[(NSEG + 1) * LDW];
__device__ float g_offSuf[NSEG * LDW];

// Monotone bucket-value map. MUST be identical fp ops for elements & thresholds
__device__ __forceinline__ float bval(float x, float dmin, float scale)
{
    return fminf(__fmul_rn(__fsub_rn(x, dmin), scale), (float)(NB - 1));
}

// ---------------------------------------------------------------------------
// Kernel A: Wh = h @ W ; s = Wh @ a1 ; d = Wh @ a2
// ---------------------------------------------------------------------------
__global__ __launch_bounds__(128) void wh_kernel(const float* __restrict__ h,
                                                 const float* __restrict__ W,
                                                 const float* __restrict__ a)
{
    __shared__ float h_sh[16][F_IN];
    __shared__ float W_sh[F_IN][F_OUT];
    __shared__ float wh_sh[16][F_OUT];
    __shared__ float a_sh[2 * F_OUT];

    const int tid = threadIdx.x;
    const int row_base = blockIdx.x * 16;

    const float4* Wv  = (const float4*)W;
    float4*       Wsv = (float4*)W_sh;
#pragma unroll
    for (int k = 0; k < 16; k++) Wsv[tid + k * 128] = Wv[tid + k * 128];

    const float4* hv  = (const float4*)(h + (size_t)row_base * F_IN);
    float4*       hsv = (float4*)h_sh;
#pragma unroll
    for (int k = 0; k < 4; k++) hsv[tid + k * 128] = hv[tid + k * 128];

    a_sh[tid] = a[tid];
    __syncthreads();

    const int c  = tid & 63;
    const int rh = tid >> 6;

    float acc[8];
#pragma unroll
    for (int r = 0; r < 8; r++) acc[r] = 0.f;

#pragma unroll 8
    for (int k = 0; k < F_IN; k++) {
        float wv = W_sh[k][c];
#pragma unroll
        for (int r = 0; r < 8; r++)
            acc[r] = fmaf(h_sh[rh * 8 + r][k], wv, acc[r]);
    }

#pragma unroll
    for (int r = 0; r < 8; r++) {
        wh_sh[rh * 8 + r][c] = acc[r];
        g_Wh[(size_t)(row_base + rh * 8 + r) * F_OUT + c] = acc[r];
    }
    __syncthreads();

    if (tid < 16) {
        float sv = 0.f, dv = 0.f;
#pragma unroll
        for (int cc = 0; cc < F_OUT; cc++) {
            float v = wh_sh[tid][cc];
            sv = fmaf(v, a_sh[cc], sv);
            dv = fmaf(v, a_sh[F_OUT + cc], dv);
        }
        g_s[row_base + tid] = sv;
        g_d[row_base + tid] = dv;
    }
}

// ---------------------------------------------------------------------------
// Kernel B: dmin/dmax of d + bucket scale (1 block)
// ---------------------------------------------------------------------------
__global__ __launch_bounds__(1024) void range_kernel()
{
    __shared__ float smx[32], smn[32];
    const int t = threadIdx.x;
    float mx = -1e30f, mn = 1e30f;
    for (int i = t; i < NR; i += 1024) {
        float v = g_d[i];
        mx = fmaxf(mx, v);
        mn = fminf(mn, v);
    }
#pragma unroll
    for (int o = 16; o; o >>= 1) {
        mx = fmaxf(mx, __shfl_xor_sync(~0u, mx, o));
        mn = fminf(mn, __shfl_xor_sync(~0u, mn, o));
    }
    if ((t & 31) == 0) { smx[t >> 5] = mx; smn[t >> 5] = mn; }
    __syncthreads();
    if (t < 32) {
        mx = smx[t]; mn = smn[t];
#pragma unroll
        for (int o = 16; o; o >>= 1) {
            mx = fmaxf(mx, __shfl_xor_sync(~0u, mx, o));
            mn = fminf(mn, __shfl_xor_sync(~0u, mn, o));
        }
        if (t == 0) {
            g_dmax = mx;
            g_dmin = mn;
            float r = mx - mn;
            g_scale = (r > 0.f) ? (float)NB * (1.f - 1e-6f) / r : 0.f;
        }
    }
}

// ---------------------------------------------------------------------------
// Kernel H: per-chunk bucket histograms (deterministic integer counts)
// ---------------------------------------------------------------------------
__global__ __launch_bounds__(CHSZ) void hist_kernel()
{
    __shared__ int hist[NB];   // 16 KB
    const int t = threadIdx.x, blk = blockIdx.x;
    for (int i = t; i < NB; i += CHSZ) hist[i] = 0;
    __syncthreads();

    const int j = blk * CHSZ + t;
    const float dmin = g_dmin, scale = g_scale;
    const int b = (int)bval(g_d[j], dmin, scale);
    g_bkt[j] = b;
    atomicAdd(&hist[b], 1);
    __syncthreads();

    for (int i = t; i < NB; i += CHSZ) g_chist[i * NCH + blk] = hist[i];
}

// ---------------------------------------------------------------------------
// Kernel O: exclusive scan of 65536 (bucket,chunk) counts (1 block).
// Rewritten: int4 loads (MLP=16/pass), warp-shuffle 2-level scan, register
// writeback. Old version was MLP=1 serial-chain, 122us.
// ---------------------------------------------------------------------------
__global__ __launch_bounds__(1024) void scanoff_kernel()
{
    __shared__ int warp_sh[32];
    const int t    = threadIdx.x;
    const int lane = t & 31, warp = t >> 5;
    const int base = t * 64;                 // 64 ints = 16 int4 per thread

    const int4* cp = (const int4*)(g_chist + base);

    // pass 1: per-thread total (independent vector loads)
    int s = 0;
#pragma unroll
    for (int i = 0; i < 16; i++) {
        int4 v = cp[i];
        s += v.x + v.y + v.z + v.w;
    }

    // inclusive warp scan of thread totals
    int inc = s;
#pragma unroll
    for (int o = 1; o < 32; o <<= 1) {
        int n = __shfl_up_sync(~0u, inc, o);
        if (lane >= o) inc += n;
    }
    if (lane == 31) warp_sh[warp] = inc;
    __syncthreads();
    if (warp == 0) {
        int ws = warp_sh[lane];
        int wi = ws;
#pragma unroll
        for (int o = 1; o < 32; o <<= 1) {
            int n = __shfl_up_sync(~0u, wi, o);
            if (lane >= o) wi += n;
        }
        warp_sh[lane] = wi - ws;             // exclusive warp offset
    }
    __syncthreads();

    int run = warp_sh[warp] + inc - s;       // exclusive prefix for this thread

    // pass 2: writeback (loads now L1-hot)
    int4* op = (int4*)(g_choff + base);
#pragma unroll
    for (int i = 0; i < 16; i++) {
        int4 v = cp[i];
        int4 o;
        o.x = run; run += v.x;
        o.y = run; run += v.y;
        o.z = run; run += v.z;
        o.w = run; run += v.w;
        op[i] = o;
        if ((i & 3) == 0)                    // (base + i*4) % 16 == 0 here
            g_off[(base + i * 4) >> 4] = o.x;
    }
    if (t == 0) g_off[NB] = NR;
}

// ---------------------------------------------------------------------------
// Kernel Sc: stable scatter into bucket order (deterministic)
// ---------------------------------------------------------------------------
__global__ __launch_bounds__(CHSZ) void scatter_kernel()
{
    __shared__ int bk[CHSZ];
    const int t = threadIdx.x, blk = blockIdx.x;
    const int j = blk * CHSZ + t;
    const int b = g_bkt[j];
    bk[t] = b;
    __syncthreads();

    int lr = 0;
#pragma unroll 8
    for (int k = 0; k < CHSZ; k++)
        lr += (k < t && bk[k] == b);

    const int pos = g_choff[b * NCH + blk] + lr;
    g_ord[pos]  = j;
    g_dord[pos] = g_d[j];
}

// ---------------------------------------------------------------------------
// Kernel S1: per-segment element scans (prefix D-weighted excl, suffix B incl)
// ---------------------------------------------------------------------------
__global__ __launch_bounds__(128) void scan_kernel()
{
    __shared__ float wh[SEGSZ][65];
    __shared__ float Bsh[SEGSZ], Dsh[SEGSZ];

    const int g = blockIdx.x;
    const int t = threadIdx.x;
    const int base = g * SEGSZ;

    const int src = g_ord[base + t];
    const float4* wr = (const float4*)(g_Wh + (size_t)src * F_OUT);
#pragma unroll
    for (int i = 0; i < 16; i++) {
        float4 v = wr[i];
        wh[t][i * 4 + 0] = v.x;
        wh[t][i * 4 + 1] = v.y;
        wh[t][i * 4 + 2] = v.z;
        wh[t][i * 4 + 3] = v.w;
    }
    const float dm = g_dmax;
    const float dv = g_dord[base + t];
    Bsh[t] = __expf(dv - dm);
    Dsh[t] = __expf(ALPHA * (dv - dm));
    __syncthreads();

    if (t < 65) {
        float acc = 0.f;
        for (int k = 0; k < SEGSZ; k++) {
            g_locPre[(size_t)(base + k) * LDW + t] = acc;
            float x = (t < 64) ? wh[k][t] : 1.f;
            acc = fmaf(Dsh[k], x, acc);
        }
        g_segPre[g * LDW + t] = acc;

        float acc2 = 0.f;
        for (int k = SEGSZ - 1; k >= 0; k--) {
            float x = (t < 64) ? wh[k][t] : 1.f;
            acc2 = fmaf(Bsh[k], x, acc2);
            g_locSuf[(size_t)(base + k) * LDW + t] = acc2;
        }
        g_segSuf[g * LDW + t] = acc2;
    }
}

// ---------------------------------------------------------------------------
// Kernel S2: scan segment totals (1 block). Rewritten: batch loads into
// registers (MLP~64) then serial register prefix. Old: serial global chain.
// ---------------------------------------------------------------------------
__global__ __launch_bounds__(128) void segscan_kernel()
{
    const int t = threadIdx.x;
    if (t >= 65) return;

    float vp[NSEG];
#pragma unroll
    for (int g = 0; g < NSEG; g++) vp[g] = g_segPre[g * LDW + t];
    float acc = 0.f;
#pragma unroll
    for (int g = 0; g < NSEG; g++) {
        g_offPre[g * LDW + t] = acc;
        acc += vp[g];
    }
    g_offPre[NSEG * LDW + t] = acc;

    float vs[NSEG];
#pragma unroll
    for (int g = 0; g < NSEG; g++) vs[g] = g_segSuf[g * LDW + t];
    float acc2 = 0.f;
#pragma unroll
    for (int g = NSEG - 1; g >= 0; g--) {
        g_offSuf[g * LDW + t] = acc2;
        acc2 += vs[g];
    }
}

// ---------------------------------------------------------------------------
// Kernel F: warp-per-row combine. Split = bucket lookup (no search);
// boundary bucket iterated exactly; coalesced reads; ELU output.
// ---------------------------------------------------------------------------
__global__ __launch_bounds__(256) void final_kernel(float* __restrict__ out)
{
    const int t = threadIdx.x;
    const int w = t >> 5, l = t & 31;
    const int i = blockIdx.x * 8 + w;

    const float s     = g_s[i];
    const float dm    = g_dmax;
    const float dmin  = g_dmin;
    const float scale = g_scale;

    const float xm = s + dm;
    const float m  = fmaxf(xm, ALPHA * xm);
    const float A  = __expf(xm - m);
    const float C  = __expf(ALPHA * xm - m);
    const float th = -s;

    const float tb = bval(th, dmin, scale);
    int e0 = 0, e1 = 0;
    if (tb >= 0.f) {
        int b = (int)tb;
        e0 = g_off[b];
        e1 = g_off[b + 1];
    }

    float pre_l, pre_h, pre_z;
    if (e0 < NR) {
        const int sg = e0 >> 7;
        const float* oP = g_offPre + sg * LDW;
        const float* lP = g_locPre + (size_t)e0 * LDW;
        pre_l = oP[l] + lP[l];
        pre_h = oP[32 + l] + lP[32 + l];
        pre_z = oP[64] + lP[64];
    } else {
        const float* oP = g_offPre + NSEG * LDW;
        pre_l = oP[l];
        pre_h = oP[32 + l];
        pre_z = oP[64];
    }

    float suf_l = 0.f, suf_h = 0.f, suf_z = 0.f;
    if (e1 < NR) {
        const int sg = e1 >> 7;
        const float* oS = g_offSuf + sg * LDW;
        const float* lS = g_locSuf + (size_t)e1 * LDW;
        suf_l = oS[l] + lS[l];
        suf_h = oS[32 + l] + lS[32 + l];
        suf_z = oS[64] + lS[64];
    }

    for (int e = e0; e < e1; e++) {
        const float de = g_dord[e];
        const int   je = g_ord[e];
        const float* wr = g_Wh + (size_t)je * F_OUT;
        const float x1 = wr[l], x2 = wr[32 + l];
        if (de <= th) {
            const float wd = __expf(ALPHA * (de - dm));
            pre_l = fmaf(wd, x1, pre_l);
            pre_h = fmaf(wd, x2, pre_h);
            pre_z += wd;
        } else {
            const float wb = __expf(de - dm);
            suf_l = fmaf(wb, x1, suf_l);
            suf_h = fmaf(wb, x2, suf_h);
            suf_z += wb;
        }
    }

    const float Z  = fmaf(A, suf_z, C * pre_z);
    const float rz = 1.f / Z;
    const float v1 = fmaf(A, suf_l, C * pre_l) * rz;
    const float v2 = fmaf(A, suf_h, C * pre_h) * rz;

    out[(size_t)i * F_OUT + l]      = (v1 > 0.f) ? v1 : expm1f(v1);
    out[(size_t)i * F_OUT + 32 + l] = (v2 > 0.f) ? v2 : expm1f(v2);
}

// ---------------------------------------------------------------------------
extern "C" void kernel_launch(void* const* d_in, const int* in_sizes, int n_in,
                              void* d_out, int out_size)
{
    const float* h = (const float*)d_in[0];
    const float* W = (const float*)d_in[1];
    const float* a = (const float*)d_in[2];
    float* out = (float*)d_out;

    wh_kernel<<<NR / 16, 128>>>(h, W, a);
    range_kernel<<<1, 1024>>>();
    hist_kernel<<<NCH, CHSZ>>>();
    scanoff_kernel<<<1, 1024>>>();
    scatter_kernel<<<NCH, CHSZ>>>();
    scan_kernel<<<NSEG, 128>>>();
    segscan_kernel<<<1, 128>>>();
    final_kernel<<<NR / 8, 256>>>(out);
}

// round 5
// speedup vs baseline: 3.7092x; 1.4738x over previous
#include <cuda_runtime.h>
#include <math.h>

#define NR    8192
#define F_IN  128
#define F_OUT 64
#define ALPHA 0.2f
#define LDW   68          // padded row stride (65 used) for scan arrays
#define NSEG  64          // 8192 / 128 element-segments
#define SEGSZ 128
#define NB    2048        // value buckets
#define NCH   8           // chunks (1024 elements each)

// ---------------- scratch (device globals; no allocs allowed) ----------------
__device__ float g_Wh[NR * F_OUT];        // 2 MB
__device__ float g_s[NR];
__device__ float g_d[NR];
__device__ float g_dmax, g_dmin, g_scale;
__device__ int   g_bkt[NR];
__device__ int   g_chist[NB * NCH];
__device__ int   g_choff[NB * NCH];
__device__ int   g_off[NB + 1];
__device__ int   g_ord[NR];
__device__ float g_dord[NR];
__device__ float g_locPre[NR * LDW];
__device__ float g_locSuf[NR * LDW];
__device__ float g_segPre[NSEG * LDW];
__device__ float g_segSuf[NSEG * LDW];
__device__ float g_offPre[(NSEG + 1) * LDW];
__device__ float g_offSuf[NSEG * LDW];

// Monotone bucket-value map. MUST be identical fp ops for elements & thresholds
__device__ __forceinline__ float bval(float x, float dmin, float scale)
{
    return fminf(__fmul_rn(__fsub_rn(x, dmin), scale), (float)(NB - 1));
}

// ---------------------------------------------------------------------------
// Kernel A: Wh = h @ W ; s = Wh @ a1 ; d = Wh @ a2
// 256 blocks x 256 threads, 32 rows/block, W streamed in 32-k chunks.
// ---------------------------------------------------------------------------
__global__ __launch_bounds__(256) void wh_kernel(const float* __restrict__ h,
                                                 const float* __restrict__ W,
                                                 const float* __restrict__ a)
{
    __shared__ float h_sh[32][F_IN];      // 16 KB
    __shared__ float W_sh[32][F_OUT];     // 8 KB (one 32-k chunk)
    __shared__ float a_sh[2 * F_OUT];
    __shared__ float sp[2][32], dp[2][32];

    const int tid  = threadIdx.x;
    const int row0 = blockIdx.x * 32;

    // load h tile: 32*128 floats = 1024 float4
    const float4* hv  = (const float4*)(h + (size_t)row0 * F_IN);
    float4*       hsv = (float4*)h_sh;
#pragma unroll
    for (int k = 0; k < 4; k++) hsv[tid + k * 256] = hv[tid + k * 256];
    if (tid < 128) a_sh[tid] = a[tid];

    const int c  = tid & 63;      // output column
    const int rh = tid >> 6;      // 0..3, 8 rows each

    float acc[8];
#pragma unroll
    for (int r = 0; r < 8; r++) acc[r] = 0.f;

#pragma unroll
    for (int kc = 0; kc < 4; kc++) {
        __syncthreads();
        // load W chunk rows [kc*32, kc*32+32): 512 float4
        const float4* Wv = (const float4*)(W + (size_t)kc * 32 * F_OUT);
        float4*      Wsv = (float4*)W_sh;
        Wsv[tid]       = Wv[tid];
        Wsv[tid + 256] = Wv[tid + 256];
        __syncthreads();

#pragma unroll
        for (int k4 = 0; k4 < 8; k4++) {
            const int kk = k4 * 4;
            float4 hr[8];
#pragma unroll
            for (int r = 0; r < 8; r++)
                hr[r] = *(const float4*)&h_sh[rh * 8 + r][kc * 32 + kk];
            const float w0 = W_sh[kk + 0][c];
            const float w1 = W_sh[kk + 1][c];
            const float w2 = W_sh[kk + 2][c];
            const float w3 = W_sh[kk + 3][c];
#pragma unroll
            for (int r = 0; r < 8; r++) {
                acc[r] = fmaf(hr[r].x, w0, acc[r]);
                acc[r] = fmaf(hr[r].y, w1, acc[r]);
                acc[r] = fmaf(hr[r].z, w2, acc[r]);
                acc[r] = fmaf(hr[r].w, w3, acc[r]);
            }
        }
    }

    // store Wh (coalesced across c)
#pragma unroll
    for (int r = 0; r < 8; r++)
        g_Wh[(size_t)(row0 + rh * 8 + r) * F_OUT + c] = acc[r];

    // s,d via warp shuffle reduce over c (each warp = 32 consecutive c's, one rh)
    const int lane = tid & 31;
    const int half = (tid >> 5) & 1;      // which 32-c half
    const float a1c = a_sh[c];
    const float a2c = a_sh[F_OUT + c];

    float sv[8], dvv[8];
#pragma unroll
    for (int r = 0; r < 8; r++) {
        float p = acc[r] * a1c;
        float q = acc[r] * a2c;
#pragma unroll
        for (int o = 16; o; o >>= 1) {
            p += __shfl_xor_sync(~0u, p, o);
            q += __shfl_xor_sync(~0u, q, o);
        }
        sv[r] = p; dvv[r] = q;
    }
    if (lane == 0) {
#pragma unroll
        for (int r = 0; r < 8; r++) {
            sp[half][rh * 8 + r] = sv[r];
            dp[half][rh * 8 + r] = dvv[r];
        }
    }
    __syncthreads();
    if (tid < 32) {
        g_s[row0 + tid] = sp[0][tid] + sp[1][tid];
        g_d[row0 + tid] = dp[0][tid] + dp[1][tid];
    }
}

// ---------------------------------------------------------------------------
// Kernel B: dmin/dmax of d + bucket scale (1 block)
// ---------------------------------------------------------------------------
__global__ __launch_bounds__(1024) void range_kernel()
{
    __shared__ float smx[32], smn[32];
    const int t = threadIdx.x;
    float mx = -1e30f, mn = 1e30f;
    for (int i = t; i < NR; i += 1024) {
        float v = g_d[i];
        mx = fmaxf(mx, v);
        mn = fminf(mn, v);
    }
#pragma unroll
    for (int o = 16; o; o >>= 1) {
        mx = fmaxf(mx, __shfl_xor_sync(~0u, mx, o));
        mn = fminf(mn, __shfl_xor_sync(~0u, mn, o));
    }
    if ((t & 31) == 0) { smx[t >> 5] = mx; smn[t >> 5] = mn; }
    __syncthreads();
    if (t < 32) {
        mx = smx[t]; mn = smn[t];
#pragma unroll
        for (int o = 16; o; o >>= 1) {
            mx = fmaxf(mx, __shfl_xor_sync(~0u, mx, o));
            mn = fminf(mn, __shfl_xor_sync(~0u, mn, o));
        }
        if (t == 0) {
            g_dmax = mx;
            g_dmin = mn;
            float r = mx - mn;
            g_scale = (r > 0.f) ? (float)NB * (1.f - 1e-6f) / r : 0.f;
        }
    }
}

// ---------------------------------------------------------------------------
// Kernel H: per-chunk histograms. 8 blocks x 1024 threads, 1 element each.
// ---------------------------------------------------------------------------
__global__ __launch_bounds__(1024) void hist_kernel()
{
    __shared__ int hist[NB];   // 8 KB
    const int t = threadIdx.x, blk = blockIdx.x;
    hist[t] = 0;
    hist[t + 1024] = 0;
    __syncthreads();

    const int j = blk * 1024 + t;
    const int b = (int)bval(g_d[j], g_dmin, g_scale);
    g_bkt[j] = b;
    atomicAdd(&hist[b], 1);
    __syncthreads();

    g_chist[(size_t)t * NCH + blk]          = hist[t];
    g_chist[(size_t)(t + 1024) * NCH + blk] = hist[t + 1024];
}

// ---------------------------------------------------------------------------
// Kernel O: exclusive scan of 16384 (bucket,chunk) counts (1 block, int4)
// ---------------------------------------------------------------------------
__global__ __launch_bounds__(1024) void scanoff_kernel()
{
    __shared__ int warp_sh[32];
    const int t    = threadIdx.x;
    const int lane = t & 31, warp = t >> 5;
    const int base = t * 16;                 // 16 ints = 4 int4 per thread

    const int4* cp = (const int4*)(g_chist + base);

    int4 v[4];
    int s = 0;
#pragma unroll
    for (int i = 0; i < 4; i++) {
        v[i] = cp[i];
        s += v[i].x + v[i].y + v[i].z + v[i].w;
    }

    int inc = s;
#pragma unroll
    for (int o = 1; o < 32; o <<= 1) {
        int n = __shfl_up_sync(~0u, inc, o);
        if (lane >= o) inc += n;
    }
    if (lane == 31) warp_sh[warp] = inc;
    __syncthreads();
    if (warp == 0) {
        int ws = warp_sh[lane];
        int wi = ws;
#pragma unroll
        for (int o = 1; o < 32; o <<= 1) {
            int n = __shfl_up_sync(~0u, wi, o);
            if (lane >= o) wi += n;
        }
        warp_sh[lane] = wi - ws;
    }
    __syncthreads();

    int run = warp_sh[warp] + inc - s;       // exclusive prefix

    int4* op = (int4*)(g_choff + base);
#pragma unroll
    for (int i = 0; i < 4; i++) {
        int4 o;
        o.x = run; run += v[i].x;
        o.y = run; run += v[i].y;
        o.z = run; run += v[i].z;
        o.w = run; run += v[i].w;
        op[i] = o;
        if ((i & 1) == 0)                    // (base + 4i) % 8 == 0
            g_off[(base + i * 4) >> 3] = o.x;
    }
    if (t == 0) g_off[NB] = NR;
}

// ---------------------------------------------------------------------------
// Kernel Sc: stable scatter, deterministic via ordered warp turns +
// __match_any_sync within-warp ranking. 8 blocks x 1024 threads (32 warps).
// ---------------------------------------------------------------------------
__global__ __launch_bounds__(1024) void scatter_kernel()
{
    __shared__ int cnt[NB];    // running position per bucket for this chunk
    const int t = threadIdx.x, blk = blockIdx.x;

    cnt[t]        = g_choff[(size_t)t * NCH + blk];
    cnt[t + 1024] = g_choff[(size_t)(t + 1024) * NCH + blk];
    __syncthreads();

    const int j  = blk * 1024 + t;
    const int b  = g_bkt[j];
    const float dv = g_d[j];
    const int lane = t & 31;
    const int warp = t >> 5;

    for (int w = 0; w < 32; w++) {
        if (warp == w) {
            unsigned mask = __match_any_sync(~0u, b);
            int leader = __ffs(mask) - 1;
            int lr = __popc(mask & ((1u << lane) - 1));
            int old = 0;
            if (lane == leader) old = atomicAdd(&cnt[b], __popc(mask));
            old = __shfl_sync(~0u, old, leader);
            const int pos = old + lr;
            g_ord[pos]  = j;
            g_dord[pos] = dv;
        }
        __syncthreads();
    }
}

// ---------------------------------------------------------------------------
// Kernel S1: per-segment element scans (prefix D-weighted excl, suffix B incl)
// ---------------------------------------------------------------------------
__global__ __launch_bounds__(128) void scan_kernel()
{
    __shared__ float wh[SEGSZ][65];
    __shared__ float Bsh[SEGSZ], Dsh[SEGSZ];

    const int g = blockIdx.x;
    const int t = threadIdx.x;
    const int base = g * SEGSZ;

    const int src = g_ord[base + t];
    const float4* wr = (const float4*)(g_Wh + (size_t)src * F_OUT);
#pragma unroll
    for (int i = 0; i < 16; i++) {
        float4 v = wr[i];
        wh[t][i * 4 + 0] = v.x;
        wh[t][i * 4 + 1] = v.y;
        wh[t][i * 4 + 2] = v.z;
        wh[t][i * 4 + 3] = v.w;
    }
    const float dm = g_dmax;
    const float dv = g_dord[base + t];
    Bsh[t] = __expf(dv - dm);
    Dsh[t] = __expf(ALPHA * (dv - dm));
    __syncthreads();

    if (t < 65) {
        float acc = 0.f;
        for (int k = 0; k < SEGSZ; k++) {
            g_locPre[(size_t)(base + k) * LDW + t] = acc;
            float x = (t < 64) ? wh[k][t] : 1.f;
            acc = fmaf(Dsh[k], x, acc);
        }
        g_segPre[g * LDW + t] = acc;

        float acc2 = 0.f;
        for (int k = SEGSZ - 1; k >= 0; k--) {
            float x = (t < 64) ? wh[k][t] : 1.f;
            acc2 = fmaf(Bsh[k], x, acc2);
            g_locSuf[(size_t)(base + k) * LDW + t] = acc2;
        }
        g_segSuf[g * LDW + t] = acc2;
    }
}

// ---------------------------------------------------------------------------
// Kernel S2: scan segment totals (1 block, register-batched)
// ---------------------------------------------------------------------------
__global__ __launch_bounds__(128) void segscan_kernel()
{
    const int t = threadIdx.x;
    if (t >= 65) return;

    float vp[NSEG];
#pragma unroll
    for (int g = 0; g < NSEG; g++) vp[g] = g_segPre[g * LDW + t];
    float acc = 0.f;
#pragma unroll
    for (int g = 0; g < NSEG; g++) {
        g_offPre[g * LDW + t] = acc;
        acc += vp[g];
    }
    g_offPre[NSEG * LDW + t] = acc;

    float vs[NSEG];
#pragma unroll
    for (int g = 0; g < NSEG; g++) vs[g] = g_segSuf[g * LDW + t];
    float acc2 = 0.f;
#pragma unroll
    for (int g = NSEG - 1; g >= 0; g--) {
        g_offSuf[g * LDW + t] = acc2;
        acc2 += vs[g];
    }
}

// ---------------------------------------------------------------------------
// Kernel F: warp-per-row combine; boundary bucket exact; ELU output.
// ---------------------------------------------------------------------------
__global__ __launch_bounds__(256) void final_kernel(float* __restrict__ out)
{
    const int t = threadIdx.x;
    const int w = t >> 5, l = t & 31;
    const int i = blockIdx.x * 8 + w;

    const float s     = g_s[i];
    const float dm    = g_dmax;
    const float dmin  = g_dmin;
    const float scale = g_scale;

    const float xm = s + dm;
    const float m  = fmaxf(xm, ALPHA * xm);
    const float A  = __expf(xm - m);
    const float C  = __expf(ALPHA * xm - m);
    const float th = -s;

    const float tb = bval(th, dmin, scale);
    int e0 = 0, e1 = 0;
    if (tb >= 0.f) {
        int b = (int)tb;
        e0 = g_off[b];
        e1 = g_off[b + 1];
    }

    float pre_l, pre_h, pre_z;
    if (e0 < NR) {
        const int sg = e0 >> 7;
        const float* oP = g_offPre + sg * LDW;
        const float* lP = g_locPre + (size_t)e0 * LDW;
        pre_l = oP[l] + lP[l];
        pre_h = oP[32 + l] + lP[32 + l];
        pre_z = oP[64] + lP[64];
    } else {
        const float* oP = g_offPre + NSEG * LDW;
        pre_l = oP[l];
        pre_h = oP[32 + l];
        pre_z = oP[64];
    }

    float suf_l = 0.f, suf_h = 0.f, suf_z = 0.f;
    if (e1 < NR) {
        const int sg = e1 >> 7;
        const float* oS = g_offSuf + sg * LDW;
        const float* lS = g_locSuf + (size_t)e1 * LDW;
        suf_l = oS[l] + lS[l];
        suf_h = oS[32 + l] + lS[32 + l];
        suf_z = oS[64] + lS[64];
    }

    for (int e = e0; e < e1; e++) {
        const float de = g_dord[e];
        const int   je = g_ord[e];
        const float* wr = g_Wh + (size_t)je * F_OUT;
        const float x1 = wr[l], x2 = wr[32 + l];
        if (de <= th) {
            const float wd = __expf(ALPHA * (de - dm));
            pre_l = fmaf(wd, x1, pre_l);
            pre_h = fmaf(wd, x2, pre_h);
            pre_z += wd;
        } else {
            const float wb = __expf(de - dm);
            suf_l = fmaf(wb, x1, suf_l);
            suf_h = fmaf(wb, x2, suf_h);
            suf_z += wb;
        }
    }

    const float Z  = fmaf(A, suf_z, C * pre_z);
    const float rz = 1.f / Z;
    const float v1 = fmaf(A, suf_l, C * pre_l) * rz;
    const float v2 = fmaf(A, suf_h, C * pre_h) * rz;

    out[(size_t)i * F_OUT + l]      = (v1 > 0.f) ? v1 : expm1f(v1);
    out[(size_t)i * F_OUT + 32 + l] = (v2 > 0.f) ? v2 : expm1f(v2);
}

// ---------------------------------------------------------------------------
extern "C" void kernel_launch(void* const* d_in, const int* in_sizes, int n_in,
                              void* d_out, int out_size)
{
    const float* h = (const float*)d_in[0];
    const float* W = (const float*)d_in[1];
    const float* a = (const float*)d_in[2];
    float* out = (float*)d_out;

    wh_kernel<<<NR / 32, 256>>>(h, W, a);
    range_kernel<<<1, 1024>>>();
    hist_kernel<<<NCH, 1024>>>();
    scanoff_kernel<<<1, 1024>>>();
    scatter_kernel<<<NCH, 1024>>>();
    scan_kernel<<<NSEG, 128>>>();
    segscan_kernel<<<1, 128>>>();
    final_kernel<<<NR / 8, 256>>>(out);
}